// round 7
// baseline (speedup 1.0000x reference)
#include <cuda_runtime.h>
#include <cuda_bf16.h>
#include <cstdint>
#include <cstddef>

// ============================================================================
// VQ-VAE nearest-code search, sm_103 via compute_103-legal mma.sync (HMMA).
//   dist[n,k] = ||e_k||^2 - 2 * x_n . e_k ; k*[n] = argmin_k
//   out = [ x_q | z_e | z_q ]
// bf16 hi/lo 3-term split GEMM (Keff = 1536) + fused per-lane argmin.
// ============================================================================

#define N_ROWS  32768
#define K_CODES 8192
#define D_DIM   512
#define MT_ROWS 128            // rows per CTA
#define NT      128            // codes per tile
#define KTILES  (K_CODES / NT) // 64
#define NCHUNK  24             // 3 segments * 8 d-chunks of 64
#define TPB     256

// ---- device scratch --------------------------------------------------------
__device__ __nv_bfloat16 g_xhi[(size_t)N_ROWS * D_DIM];
__device__ __nv_bfloat16 g_xlo[(size_t)N_ROWS * D_DIM];
__device__ __nv_bfloat16 g_ehi[(size_t)K_CODES * D_DIM];
__device__ __nv_bfloat16 g_elo[(size_t)K_CODES * D_DIM];
__device__ float         g_enorm[K_CODES];

// ---- SMEM layout (bytes, relative to dynamic base) -------------------------
#define OFF_A0   0u            // 128 x 128B = 16 KB
#define OFF_A1   16384u
#define OFF_B0   32768u        // 128 x 128B = 16 KB
#define OFF_B1   49152u
#define OFF_EN   65536u        // 8192 floats = 32 KB
#define OFF_RV   98304u        // 256 floats
#define OFF_RK   99328u        // 256 ints
#define OFF_KSH  100352u       // 128 ints
#define SMEM_TOTAL 100864u

#define SWZ(x) ((x) ^ (((x) >> 3) & 0x70))

__device__ __forceinline__ uint32_t smem_to_u32(const void* p) {
    uint32_t a;
    asm("{ .reg .u64 t; cvta.to.shared.u64 t, %1; cvt.u32.u64 %0, t; }"
        : "=r"(a) : "l"(p));
    return a;
}

#define CP_ASYNC16(dst, src) \
    asm volatile("cp.async.cg.shared.global [%0], [%1], 16;" \
                 :: "r"(dst), "l"(src) : "memory")
#define CP_COMMIT() asm volatile("cp.async.commit_group;" ::: "memory")
#define CP_WAIT1()  asm volatile("cp.async.wait_group 1;" ::: "memory")
#define CP_WAIT0()  asm volatile("cp.async.wait_group 0;" ::: "memory")

#define LDSM4(r0, r1, r2, r3, addr) \
    asm volatile("ldmatrix.sync.aligned.m8n8.x4.shared.b16 {%0,%1,%2,%3}, [%4];" \
                 : "=r"(r0), "=r"(r1), "=r"(r2), "=r"(r3) : "r"(addr))

#define MMA16816(c, a, b) \
    asm volatile("mma.sync.aligned.m16n8k16.row.col.f32.bf16.bf16.f32 " \
                 "{%0,%1,%2,%3}, {%4,%5,%6,%7}, {%8,%9}, {%0,%1,%2,%3};" \
                 : "+f"((c)[0]), "+f"((c)[1]), "+f"((c)[2]), "+f"((c)[3]) \
                 : "r"((a)[0]), "r"((a)[1]), "r"((a)[2]), "r"((a)[3]), \
                   "r"((b)[0]), "r"((b)[1]))

// ============================================================================
// Prep kernels
// ============================================================================
__global__ void prep_split(const float* __restrict__ src,
                           __nv_bfloat16* __restrict__ hi,
                           __nv_bfloat16* __restrict__ lo, int n4) {
    int i = blockIdx.x * blockDim.x + threadIdx.x;
    if (i >= n4) return;
    float4 v = reinterpret_cast<const float4*>(src)[i];
    __nv_bfloat16 h0 = __float2bfloat16(v.x);
    __nv_bfloat16 h1 = __float2bfloat16(v.y);
    __nv_bfloat16 h2 = __float2bfloat16(v.z);
    __nv_bfloat16 h3 = __float2bfloat16(v.w);
    __nv_bfloat16 l0 = __float2bfloat16(v.x - __bfloat162float(h0));
    __nv_bfloat16 l1 = __float2bfloat16(v.y - __bfloat162float(h1));
    __nv_bfloat16 l2 = __float2bfloat16(v.z - __bfloat162float(h2));
    __nv_bfloat16 l3 = __float2bfloat16(v.w - __bfloat162float(h3));
    __nv_bfloat162 hh0; hh0.x = h0; hh0.y = h1;
    __nv_bfloat162 hh1; hh1.x = h2; hh1.y = h3;
    __nv_bfloat162 ll0; ll0.x = l0; ll0.y = l1;
    __nv_bfloat162 ll1; ll1.x = l2; ll1.y = l3;
    reinterpret_cast<__nv_bfloat162*>(hi)[2 * i]     = hh0;
    reinterpret_cast<__nv_bfloat162*>(hi)[2 * i + 1] = hh1;
    reinterpret_cast<__nv_bfloat162*>(lo)[2 * i]     = ll0;
    reinterpret_cast<__nv_bfloat162*>(lo)[2 * i + 1] = ll1;
}

__global__ void prep_enorm(const float* __restrict__ emb) {
    __shared__ float red[128];
    int row = blockIdx.x;
    const float* e = emb + (size_t)row * D_DIM;
    float s = 0.0f;
    for (int j = threadIdx.x; j < D_DIM; j += 128) {
        float v = e[j];
        s += v * v;
    }
    red[threadIdx.x] = s;
    __syncthreads();
    for (int off = 64; off > 0; off >>= 1) {
        if (threadIdx.x < off) red[threadIdx.x] += red[threadIdx.x + off];
        __syncthreads();
    }
    if (threadIdx.x == 0) g_enorm[row] = red[0];
}

// ============================================================================
// Main kernel
// ============================================================================
__global__ void __launch_bounds__(TPB, 2)
vq_main(const float* __restrict__ x, const float* __restrict__ emb,
        float* __restrict__ out) {
    extern __shared__ char smem[];
    const uint32_t sb = smem_to_u32(smem);
    const int tid = threadIdx.x;
    const int lane = tid & 31;
    const int wid = tid >> 5;
    const int warp_m = wid & 3;     // 4 warps along M (32 rows each)
    const int warp_n = wid >> 2;    // 2 warps along N (64 codes each)
    const int rowg0 = blockIdx.x * MT_ROWS;

    // stage all 8192 e-norms
    {
        const float4* src = reinterpret_cast<const float4*>(g_enorm);
        float4* dst = reinterpret_cast<float4*>(smem + OFF_EN);
        #pragma unroll
        for (int i = 0; i < 8; i++) dst[tid + i * TPB] = src[tid + i * TPB];
    }

    float acc[2][8][4];
    #pragma unroll
    for (int mt = 0; mt < 2; mt++)
        #pragma unroll
        for (int nt = 0; nt < 8; nt++)
            #pragma unroll
            for (int q = 0; q < 4; q++) acc[mt][nt][q] = 0.0f;

    float bv[4]; int bk[4];
    #pragma unroll
    for (int i = 0; i < 4; i++) { bv[i] = 3.4e38f; bk[i] = 0; }

    // per-thread staging indices (16B granules, rows of 128B)
    const int lrow = tid >> 3;   // 0..31
    const int lj = tid & 7;      // 0..7

    auto issue = [&](int tile, int c, uint32_t abase, uint32_t bbase) {
        const int seg = c >> 3;
        const int d0 = (c & 7) << 6;
        const __nv_bfloat16* asrc = (seg == 1) ? g_xlo : g_xhi;
        const __nv_bfloat16* bsrc = (seg == 2) ? g_elo : g_ehi;
        #pragma unroll
        for (int p = 0; p < 4; p++) {
            int r = p * 32 + lrow;
            const void* s = asrc + (size_t)(rowg0 + r) * D_DIM + d0 + lj * 8;
            CP_ASYNC16(abase + SWZ(r * 128 + lj * 16), s);
        }
        #pragma unroll
        for (int p = 0; p < 4; p++) {
            int r = p * 32 + lrow;
            const void* s = bsrc + (size_t)(tile * NT + r) * D_DIM + d0 + lj * 8;
            CP_ASYNC16(bbase + SWZ(r * 128 + lj * 16), s);
        }
    };

    // ldmatrix per-lane address components (invariant across the main loop)
    const int arow = warp_m * 32 + (lane & 7) + ((lane >> 3) & 1) * 8; // + mt*16
    const int acol = (lane & 16) ? 16 : 0;
    const int brow = warp_n * 64 + (lane & 7) + ((lane & 16) ? 8 : 0); // + np*16
    const int bcol = (lane & 8) ? 16 : 0;
    uint32_t a_off[2], b_off[4];
    #pragma unroll
    for (int mt = 0; mt < 2; mt++)
        a_off[mt] = (uint32_t)((arow + mt * 16) * 128 + acol);
    #pragma unroll
    for (int np = 0; np < 4; np++)
        b_off[np] = (uint32_t)((brow + np * 16) * 128 + bcol);

    // prime pipeline
    issue(0, 0, sb + OFF_A0, sb + OFF_B0);
    CP_COMMIT();

    #pragma unroll 1
    for (int tile = 0; tile < KTILES; tile++) {
        #pragma unroll 1
        for (int c = 0; c < NCHUNK; c++) {
            const int gi = tile * NCHUNK + c;
            if (gi + 1 < KTILES * NCHUNK) {
                int nc = c + 1, ntile = tile;
                if (nc == NCHUNK) { nc = 0; ntile++; }
                const uint32_t ab = sb + (((gi + 1) & 1) ? OFF_A1 : OFF_A0);
                const uint32_t bb = sb + (((gi + 1) & 1) ? OFF_B1 : OFF_B0);
                issue(ntile, nc, ab, bb);
                CP_COMMIT();
                CP_WAIT1();
            } else {
                CP_WAIT0();
            }
            __syncthreads();

            const uint32_t abuf = sb + ((gi & 1) ? OFF_A1 : OFF_A0);
            const uint32_t bbuf = sb + ((gi & 1) ? OFF_B1 : OFF_B0);

            #pragma unroll
            for (int ks = 0; ks < 4; ks++) {
                uint32_t a[2][4];
                #pragma unroll
                for (int mt = 0; mt < 2; mt++) {
                    uint32_t ad = abuf + SWZ(a_off[mt] + ks * 32);
                    LDSM4(a[mt][0], a[mt][1], a[mt][2], a[mt][3], ad);
                }
                uint32_t b[8][2];
                #pragma unroll
                for (int np = 0; np < 4; np++) {
                    uint32_t bd = bbuf + SWZ(b_off[np] + ks * 32);
                    uint32_t r0, r1, r2, r3;
                    LDSM4(r0, r1, r2, r3, bd);
                    b[np * 2][0] = r0;     b[np * 2][1] = r1;
                    b[np * 2 + 1][0] = r2; b[np * 2 + 1][1] = r3;
                }
                #pragma unroll
                for (int mt = 0; mt < 2; mt++)
                    #pragma unroll
                    for (int nt = 0; nt < 8; nt++)
                        MMA16816(acc[mt][nt], a[mt], b[nt]);
            }
            __syncthreads();
        }

        // --- per-tile argmin epilogue (registers + enorm smem) ---
        const float* en = (const float*)(smem + OFF_EN);
        const int colb = tile * NT + warp_n * 64 + (lane & 3) * 2;
        #pragma unroll
        for (int nt = 0; nt < 8; nt++) {
            float2 e2 = *(const float2*)(en + colb + nt * 8);
            const int k0 = colb + nt * 8;
            #pragma unroll
            for (int mt = 0; mt < 2; mt++)
                #pragma unroll
                for (int h = 0; h < 2; h++) {
                    const int bi = mt * 2 + h;
                    float d0 = e2.x - 2.0f * acc[mt][nt][h * 2];
                    float d1 = e2.y - 2.0f * acc[mt][nt][h * 2 + 1];
                    if (d0 < bv[bi]) { bv[bi] = d0; bk[bi] = k0; }
                    if (d1 < bv[bi]) { bv[bi] = d1; bk[bi] = k0 + 1; }
                }
        }
        #pragma unroll
        for (int mt = 0; mt < 2; mt++)
            #pragma unroll
            for (int nt = 0; nt < 8; nt++)
                #pragma unroll
                for (int q = 0; q < 4; q++) acc[mt][nt][q] = 0.0f;
    }

    // --- cross-lane / cross-warp argmin reduce ---
    float* sRV = (float*)(smem + OFF_RV);
    int*   sRK = (int*)(smem + OFF_RK);
    #pragma unroll
    for (int bi = 0; bi < 4; bi++) {
        float v = bv[bi]; int k = bk[bi];
        #pragma unroll
        for (int off = 1; off < 4; off <<= 1) {
            float ov = __shfl_xor_sync(0xFFFFFFFFu, v, off);
            int   ok = __shfl_xor_sync(0xFFFFFFFFu, k, off);
            if (ov < v || (ov == v && ok < k)) { v = ov; k = ok; }
        }
        if ((lane & 3) == 0) {
            const int mt = bi >> 1, h = bi & 1;
            const int rl = warp_m * 32 + mt * 16 + (lane >> 2) + h * 8;
            sRV[rl * 2 + warp_n] = v;
            sRK[rl * 2 + warp_n] = k;
        }
    }
    __syncthreads();
    int* sK = (int*)(smem + OFF_KSH);
    if (tid < MT_ROWS) {
        float v0 = sRV[tid * 2], v1 = sRV[tid * 2 + 1];
        int k0 = sRK[tid * 2], k1 = sRK[tid * 2 + 1];
        sK[tid] = (v1 < v0 || (v1 == v0 && k1 < k0)) ? k1 : k0;
    }
    __syncthreads();

    // --- outputs: [x_q | z_e | z_q] ---
    const size_t ND = (size_t)N_ROWS * D_DIM;
    const int half = tid >> 7;      // 0/1
    const int cv = tid & 127;       // float4 index within 512-col row
    #pragma unroll 1
    for (int rr = 0; rr < 64; rr++) {
        const int r = rr * 2 + half;
        const int R = rowg0 + r;
        const int k = sK[r];
        float4 xv = reinterpret_cast<const float4*>(x + (size_t)R * D_DIM)[cv];
        float4 ev = reinterpret_cast<const float4*>(emb + (size_t)k * D_DIM)[cv];
        float4 fq;
        fq.x = xv.x + (ev.x - xv.x);
        fq.y = xv.y + (ev.y - xv.y);
        fq.z = xv.z + (ev.z - xv.z);
        fq.w = xv.w + (ev.w - xv.w);
        reinterpret_cast<float4*>(out + (size_t)R * D_DIM)[cv]          = fq;
        reinterpret_cast<float4*>(out + ND + (size_t)R * D_DIM)[cv]     = xv;
        reinterpret_cast<float4*>(out + 2 * ND + (size_t)R * D_DIM)[cv] = ev;
    }
}

// ============================================================================
// Launch
// ============================================================================
extern "C" void kernel_launch(void* const* d_in, const int* in_sizes, int n_in,
                              void* d_out, int out_size) {
    const float* x   = (const float*)d_in[0];
    const float* emb = (const float*)d_in[1];
    float* out = (float*)d_out;
    (void)in_sizes; (void)n_in; (void)out_size;

    cudaFuncSetAttribute(vq_main, cudaFuncAttributeMaxDynamicSharedMemorySize,
                         (int)SMEM_TOTAL);

    __nv_bfloat16 *xhi, *xlo, *ehi, *elo;
    cudaGetSymbolAddress((void**)&xhi, g_xhi);
    cudaGetSymbolAddress((void**)&xlo, g_xlo);
    cudaGetSymbolAddress((void**)&ehi, g_ehi);
    cudaGetSymbolAddress((void**)&elo, g_elo);

    {
        int n4 = (N_ROWS * D_DIM) / 4;
        prep_split<<<n4 / 256, 256>>>(x, xhi, xlo, n4);
    }
    {
        int n4 = (K_CODES * D_DIM) / 4;
        prep_split<<<n4 / 256, 256>>>(emb, ehi, elo, n4);
    }
    prep_enorm<<<K_CODES, 128>>>(emb);

    vq_main<<<N_ROWS / MT_ROWS, TPB, SMEM_TOTAL>>>(x, emb, out);
}

// round 10
// speedup vs baseline: 1.3676x; 1.3676x over previous
#include <cuda_runtime.h>
#include <cuda_bf16.h>
#include <cstdint>
#include <cstddef>

// ============================================================================
// VQ-VAE nearest-code search, filter + exact-recheck architecture.
//  Phase 1: bf16x1 HMMA GEMM  approx dist[n,k] = ||e_k||^2 - 2 x.e  -> per-row
//           per-32-code-subtile minima (g_submin).
//  Phase 2: rowmin+margin threshold; rescan flagged subtiles exactly in fp32;
//           atomicMin packed (dist,k) -> exact argmin.
//  Phase 3: gather + write [x_q | z_e | z_q].
// ============================================================================

#define N_ROWS  32768
#define K_CODES 8192
#define D_DIM   512
#define MT_ROWS 128
#define NT      128                 // codes per tile
#define KTILES  (K_CODES / NT)      // 64
#define NCH_TOT (KTILES * 8)        // 512 chunks of 64 d-elems
#define TPB     256
#define NSUB    256                 // 32-code subtiles
#define MARGIN  0.125f

// ---- device scratch --------------------------------------------------------
__device__ __nv_bfloat16 g_xbf[(size_t)N_ROWS * D_DIM];
__device__ __nv_bfloat16 g_ebf[(size_t)K_CODES * D_DIM];
__device__ float         g_enorm[K_CODES];
__device__ float         g_submin[(size_t)NSUB * N_ROWS];   // [sub][row]
__device__ float         g_thresh[N_ROWS];
__device__ unsigned long long g_best[N_ROWS];

// ---- GEMM smem layout: enorm tile + 3-stage A/B buffers --------------------
#define OFF_EN   0u                       // 128 floats (512B), pad to 1024
#define OFF_A(s) (1024u + (uint32_t)(s) * 16384u)     // 3 x 16KB
#define OFF_B(s) (50176u + (uint32_t)(s) * 16384u)    // 3 x 16KB
#define SMEM_GEMM 99328u

#define SWZ(x) ((x) ^ (((x) >> 3) & 0x70))

__device__ __forceinline__ uint32_t smem_to_u32(const void* p) {
    uint32_t a;
    asm("{ .reg .u64 t; cvta.to.shared.u64 t, %1; cvt.u32.u64 %0, t; }"
        : "=r"(a) : "l"(p));
    return a;
}

#define CP_ASYNC16(dst, src) \
    asm volatile("cp.async.cg.shared.global [%0], [%1], 16;" \
                 :: "r"(dst), "l"(src) : "memory")
#define CP_COMMIT() asm volatile("cp.async.commit_group;" ::: "memory")
#define CP_WAIT1()  asm volatile("cp.async.wait_group 1;" ::: "memory")
#define CP_WAIT0()  asm volatile("cp.async.wait_group 0;" ::: "memory")

#define LDSM4(r0, r1, r2, r3, addr) \
    asm volatile("ldmatrix.sync.aligned.m8n8.x4.shared.b16 {%0,%1,%2,%3}, [%4];" \
                 : "=r"(r0), "=r"(r1), "=r"(r2), "=r"(r3) : "r"(addr))

#define MMA16816(c, a, b) \
    asm volatile("mma.sync.aligned.m16n8k16.row.col.f32.bf16.bf16.f32 " \
                 "{%0,%1,%2,%3}, {%4,%5,%6,%7}, {%8,%9}, {%0,%1,%2,%3};" \
                 : "+f"((c)[0]), "+f"((c)[1]), "+f"((c)[2]), "+f"((c)[3]) \
                 : "r"((a)[0]), "r"((a)[1]), "r"((a)[2]), "r"((a)[3]), \
                   "r"((b)[0]), "r"((b)[1]))

// ============================================================================
// Prep kernels
// ============================================================================
__global__ void prep_bf16(const float* __restrict__ src,
                          __nv_bfloat16* __restrict__ dst, int n4) {
    int i = blockIdx.x * blockDim.x + threadIdx.x;
    if (i >= n4) return;
    float4 v = reinterpret_cast<const float4*>(src)[i];
    __nv_bfloat162 h0; h0.x = __float2bfloat16(v.x); h0.y = __float2bfloat16(v.y);
    __nv_bfloat162 h1; h1.x = __float2bfloat16(v.z); h1.y = __float2bfloat16(v.w);
    reinterpret_cast<__nv_bfloat162*>(dst)[2 * i]     = h0;
    reinterpret_cast<__nv_bfloat162*>(dst)[2 * i + 1] = h1;
}

__global__ void prep_enorm(const float* __restrict__ emb) {
    __shared__ float red[128];
    int row = blockIdx.x;
    const float* e = emb + (size_t)row * D_DIM;
    float s = 0.0f;
    for (int j = threadIdx.x; j < D_DIM; j += 128) {
        float v = e[j];
        s += v * v;
    }
    red[threadIdx.x] = s;
    __syncthreads();
    for (int off = 64; off > 0; off >>= 1) {
        if (threadIdx.x < off) red[threadIdx.x] += red[threadIdx.x + off];
        __syncthreads();
    }
    if (threadIdx.x == 0) g_enorm[row] = red[0];
}

// ============================================================================
// Phase 1: bf16x1 GEMM + per-subtile approx-dist minima
// ============================================================================
__global__ void __launch_bounds__(TPB, 2)
vq_gemm(float* __restrict__ dummy) {
    extern __shared__ char smem[];
    const uint32_t sb = smem_to_u32(smem);
    const int tid = threadIdx.x;
    const int lane = tid & 31;
    const int wid = tid >> 5;
    const int warp_m = wid & 3;     // 4 warps along M (32 rows each)
    const int warp_n = wid >> 2;    // 2 warps along N (64 codes each)
    const int rowg0 = blockIdx.x * MT_ROWS;

    float acc[2][8][4];
    #pragma unroll
    for (int mt = 0; mt < 2; mt++)
        #pragma unroll
        for (int nt = 0; nt < 8; nt++)
            #pragma unroll
            for (int q = 0; q < 4; q++) acc[mt][nt][q] = 0.0f;

    // staging indices (16B granules, 128B rows)
    const int lrow = tid >> 3;   // 0..31
    const int lj = tid & 7;      // 0..7

    auto issue = [&](int gi2) {
        const int tile = gi2 >> 3;
        const int d0 = (gi2 & 7) << 6;
        const int s3 = gi2 % 3;
        const uint32_t abase = sb + OFF_A(s3);
        const uint32_t bbase = sb + OFF_B(s3);
        #pragma unroll
        for (int p = 0; p < 4; p++) {
            int r = p * 32 + lrow;
            const void* s = g_xbf + (size_t)(rowg0 + r) * D_DIM + d0 + lj * 8;
            CP_ASYNC16(abase + SWZ(r * 128 + lj * 16), s);
        }
        #pragma unroll
        for (int p = 0; p < 4; p++) {
            int r = p * 32 + lrow;
            const void* s = g_ebf + (size_t)(tile * NT + r) * D_DIM + d0 + lj * 8;
            CP_ASYNC16(bbase + SWZ(r * 128 + lj * 16), s);
        }
    };

    // ldmatrix per-lane address components (loop-invariant)
    const int arow = warp_m * 32 + (lane & 7) + ((lane >> 3) & 1) * 8;
    const int acol = (lane & 16) ? 16 : 0;
    const int brow = warp_n * 64 + (lane & 7) + ((lane & 16) ? 8 : 0);
    const int bcol = (lane & 8) ? 16 : 0;
    uint32_t a_off[2], b_off[4];
    #pragma unroll
    for (int mt = 0; mt < 2; mt++)
        a_off[mt] = (uint32_t)((arow + mt * 16) * 128 + acol);
    #pragma unroll
    for (int np = 0; np < 4; np++)
        b_off[np] = (uint32_t)((brow + np * 16) * 128 + bcol);

    issue(0); CP_COMMIT();
    issue(1); CP_COMMIT();

    #pragma unroll 1
    for (int gi = 0; gi < NCH_TOT; gi++) {
        if (gi + 2 < NCH_TOT) CP_WAIT1(); else CP_WAIT0();
        __syncthreads();   // buffers ready for all; prior compute/epilogue done

        if ((gi & 7) == 0 && tid < NT)
            ((float*)(smem + OFF_EN))[tid] = g_enorm[(gi >> 3) * NT + tid];

        if (gi + 2 < NCH_TOT) { issue(gi + 2); CP_COMMIT(); }

        const int s3 = gi % 3;
        const uint32_t abuf = sb + OFF_A(s3);
        const uint32_t bbuf = sb + OFF_B(s3);

        #pragma unroll
        for (int ks = 0; ks < 4; ks++) {
            uint32_t a[2][4];
            #pragma unroll
            for (int mt = 0; mt < 2; mt++) {
                uint32_t ad = abuf + SWZ(a_off[mt] + ks * 32);
                LDSM4(a[mt][0], a[mt][1], a[mt][2], a[mt][3], ad);
            }
            uint32_t b[8][2];
            #pragma unroll
            for (int np = 0; np < 4; np++) {
                uint32_t bd = bbuf + SWZ(b_off[np] + ks * 32);
                uint32_t r0, r1, r2, r3;
                LDSM4(r0, r1, r2, r3, bd);
                b[np * 2][0] = r0;     b[np * 2][1] = r1;
                b[np * 2 + 1][0] = r2; b[np * 2 + 1][1] = r3;
            }
            #pragma unroll
            for (int mt = 0; mt < 2; mt++)
                #pragma unroll
                for (int nt = 0; nt < 8; nt++)
                    MMA16816(acc[mt][nt], a[mt], b[nt]);
        }

        if ((gi & 7) == 7) {
            // epilogue: per (row, 32-code subtile) approx-dist min
            const int tile = gi >> 3;
            const float* en = (const float*)(smem + OFF_EN);
            #pragma unroll
            for (int s = 0; s < 2; s++) {
                #pragma unroll
                for (int mt = 0; mt < 2; mt++) {
                    #pragma unroll
                    for (int h = 0; h < 2; h++) {
                        float mb = 3.4e38f;
                        #pragma unroll
                        for (int nt = s * 4; nt < s * 4 + 4; nt++) {
                            float2 e2 = *(const float2*)(
                                en + warp_n * 64 + nt * 8 + (lane & 3) * 2);
                            float d0 = e2.x - 2.0f * acc[mt][nt][h * 2];
                            float d1 = e2.y - 2.0f * acc[mt][nt][h * 2 + 1];
                            mb = fminf(mb, fminf(d0, d1));
                        }
                        mb = fminf(mb, __shfl_xor_sync(0xFFFFFFFFu, mb, 1));
                        mb = fminf(mb, __shfl_xor_sync(0xFFFFFFFFu, mb, 2));
                        if ((lane & 3) == 0) {
                            int sub = tile * 4 + warp_n * 2 + s;
                            int row = rowg0 + warp_m * 32 + mt * 16 +
                                      (lane >> 2) + h * 8;
                            g_submin[(size_t)sub * N_ROWS + row] = mb;
                        }
                    }
                }
            }
            #pragma unroll
            for (int mt = 0; mt < 2; mt++)
                #pragma unroll
                for (int nt = 0; nt < 8; nt++)
                    #pragma unroll
                    for (int q = 0; q < 4; q++) acc[mt][nt][q] = 0.0f;
        }
    }
    (void)dummy;
}

// ============================================================================
// Phase 2a: per-row threshold + init best
// ============================================================================
__global__ void vq_rowmin() {
    int row = blockIdx.x * blockDim.x + threadIdx.x;
    float mn = 3.4e38f;
    #pragma unroll 4
    for (int s = 0; s < NSUB; s++)
        mn = fminf(mn, g_submin[(size_t)s * N_ROWS + row]);
    g_thresh[row] = mn + MARGIN;
    g_best[row] = 0xFFFFFFFFFFFFFFFFull;
}

// ============================================================================
// Phase 2b: exact fp32 rescan of flagged (row, subtile) pairs
// ============================================================================
#define ROWG 4096
#define SMEM_B (65536u + 128u + (uint32_t)ROWG * 4u + 16u)

__global__ void __launch_bounds__(256)
vq_rescan(const float* __restrict__ x, const float* __restrict__ emb) {
    extern __shared__ char smem[];
    float4* es4 = (float4*)smem;                       // 32 codes x 512 fp32
    float* en_s = (float*)(smem + 65536);              // 32 norms
    int* list = (int*)(smem + 65536 + 128);            // flagged rows
    int* cnt = (int*)(smem + 65536 + 128 + ROWG * 4);

    const int t = threadIdx.x;
    const int st = blockIdx.x;         // subtile 0..255
    const int rg = blockIdx.y;         // row group

    // stage e subtile (fp32) + norms
    const float4* emb4 = (const float4*)emb;
    #pragma unroll
    for (int i = 0; i < 16; i++) {
        int idx = i * 256 + t;         // 4096 float4
        es4[idx] = emb4[(size_t)st * 4096 + idx];
    }
    if (t < 32) en_s[t] = g_enorm[st * 32 + t];
    if (t == 0) *cnt = 0;
    __syncthreads();

    // flag scan
    const int rowbase = rg * ROWG;
    #pragma unroll 1
    for (int it = 0; it < ROWG / 256; it++) {
        int row = rowbase + it * 256 + t;
        if (g_submin[(size_t)st * N_ROWS + row] <= g_thresh[row]) {
            int p = atomicAdd(cnt, 1);
            list[p] = row;
        }
    }
    __syncthreads();

    const int n = *cnt;
    const int code = t >> 3;           // 0..31
    const int part = t & 7;            // 0..7
    const float4* x4 = (const float4*)x;
    #pragma unroll 1
    for (int i = 0; i < n; i++) {
        int row = list[i];
        const float4* xr = x4 + (size_t)row * 128;
        float s = 0.0f;
        #pragma unroll
        for (int j = 0; j < 16; j++) {
            float4 a = xr[part * 16 + j];
            float4 b = es4[code * 128 + part * 16 + j];
            s += a.x * b.x + a.y * b.y + a.z * b.z + a.w * b.w;
        }
        s += __shfl_down_sync(0xFFFFFFFFu, s, 4, 8);
        s += __shfl_down_sync(0xFFFFFFFFu, s, 2, 8);
        s += __shfl_down_sync(0xFFFFFFFFu, s, 1, 8);
        if (part == 0) {
            float dist = en_s[code] - 2.0f * s;
            unsigned u = __float_as_uint(dist);
            u = (u & 0x80000000u) ? ~u : (u | 0x80000000u);
            unsigned long long pk =
                ((unsigned long long)u << 32) | (unsigned)(st * 32 + code);
            atomicMin(&g_best[row], pk);
        }
    }
}

// ============================================================================
// Phase 3: outputs [x_q | z_e | z_q]
// ============================================================================
__global__ void vq_out(const float* __restrict__ x,
                       const float* __restrict__ emb,
                       float* __restrict__ out) {
    const size_t u = (size_t)blockIdx.x * 256 + threadIdx.x;  // row*128 + cv
    const int row = (int)(u >> 7);
    const int cv = (int)(u & 127);
    const int k = (int)(unsigned)(g_best[row] & 0xFFFFFFFFull);
    const float4* x4 = (const float4*)x;
    const float4* e4 = (const float4*)emb;
    float4* o4 = (float4*)out;
    const size_t ND4 = (size_t)N_ROWS * 128;
    float4 xv = x4[(size_t)row * 128 + cv];
    float4 ev = e4[(size_t)k * 128 + cv];
    float4 fq;
    fq.x = xv.x + (ev.x - xv.x);
    fq.y = xv.y + (ev.y - xv.y);
    fq.z = xv.z + (ev.z - xv.z);
    fq.w = xv.w + (ev.w - xv.w);
    o4[u] = fq;
    o4[ND4 + u] = xv;
    o4[2 * ND4 + u] = ev;
}

// ============================================================================
// Launch
// ============================================================================
extern "C" void kernel_launch(void* const* d_in, const int* in_sizes, int n_in,
                              void* d_out, int out_size) {
    const float* x   = (const float*)d_in[0];
    const float* emb = (const float*)d_in[1];
    float* out = (float*)d_out;
    (void)in_sizes; (void)n_in; (void)out_size;

    cudaFuncSetAttribute(vq_gemm, cudaFuncAttributeMaxDynamicSharedMemorySize,
                         (int)SMEM_GEMM);
    cudaFuncSetAttribute(vq_rescan, cudaFuncAttributeMaxDynamicSharedMemorySize,
                         (int)SMEM_B);

    __nv_bfloat16 *xbf, *ebf;
    cudaGetSymbolAddress((void**)&xbf, g_xbf);
    cudaGetSymbolAddress((void**)&ebf, g_ebf);

    {
        int n4 = (N_ROWS * D_DIM) / 4;
        prep_bf16<<<n4 / 256, 256>>>(x, xbf, n4);
    }
    {
        int n4 = (K_CODES * D_DIM) / 4;
        prep_bf16<<<n4 / 256, 256>>>(emb, ebf, n4);
    }
    prep_enorm<<<K_CODES, 128>>>(emb);

    vq_gemm<<<N_ROWS / MT_ROWS, TPB, SMEM_GEMM>>>(out);

    vq_rowmin<<<N_ROWS / 256, 256>>>();

    dim3 gb(NSUB, N_ROWS / ROWG);
    vq_rescan<<<gb, 256, SMEM_B>>>(x, emb);

    vq_out<<<(N_ROWS * 128) / 256, 256>>>(x, emb, out);
}